// round 5
// baseline (speedup 1.0000x reference)
#include <cuda_runtime.h>
#include <cstdint>

// Shapes (fixed by the problem)
#define B 8
#define D 256
#define HW (128 * 128)        // 16384
#define C 80
#define NPIX (B * HW)         // 131072
#define RANGE_EXTENDER 10.0f
#define EPS 1e-8f

#define NTHREADS 320          // 16 px-cols x 20 ch-rows
#define PXT 128               // pixels per block (16 cols * 8 px)

typedef unsigned long long u64;

// Duplicated pre-scaled weights: g_w2[d*C + c] = {v, v}, v = w[c][d]/||w_c||*asf[c]*10
// Stored as float2 so each LDG.128 yields two packed duplicated channels.
__device__ float2 g_w2[D * C];

// ---------------------------------------------------------------------------
// Packed fp32x2 helpers
// ---------------------------------------------------------------------------
__device__ __forceinline__ u64 fma2(u64 a, u64 b, u64 c) {
    u64 d;
    asm("fma.rn.f32x2 %0, %1, %2, %3;" : "=l"(d) : "l"(a), "l"(b), "l"(c));
    return d;
}
__device__ __forceinline__ void unpack2(u64 v, float& lo, float& hi) {
    asm("mov.b64 {%0, %1}, %2;" : "=f"(lo), "=f"(hi) : "l"(v));
}

// ---------------------------------------------------------------------------
// Kernel 1: normalize + scale weights, transpose + duplicate to [D][C] pairs
// ---------------------------------------------------------------------------
__global__ void prep_weights_kernel(const float* __restrict__ w,
                                    const float* __restrict__ asf) {
    int c = blockIdx.x;
    int d = threadIdx.x;
    float v = w[c * D + d];

    __shared__ float red[D];
    red[d] = v * v;
    __syncthreads();
    #pragma unroll
    for (int s = D / 2; s > 0; s >>= 1) {
        if (d < s) red[d] += red[d + s];
        __syncthreads();
    }
    float norm = sqrtf(red[0]);
    float scale = asf[c] * RANGE_EXTENDER / fmaxf(norm, EPS);
    float vs = v * scale;
    g_w2[d * C + c] = make_float2(vs, vs);
}

// ---------------------------------------------------------------------------
// Kernel 2: pack-free f32x2 GEMM, no smem staging, no mainloop barriers.
// Thread (px_col 0..15, ch_row 0..19): 8 pixels (4 packed pairs) x 4 channels.
// x pairs come packed from LDG.128; duplicated w pairs come packed from
// LDG.128 on g_w2. Inner loop = 4 LDG.128 + 16 fma2.
// ---------------------------------------------------------------------------
__global__ __launch_bounds__(NTHREADS, 2)
void coshead_main_kernel(const float* __restrict__ x, float* __restrict__ out) {
    __shared__ float norms[PXT];

    const int tid    = threadIdx.x;
    const int px_col = tid & 15;         // 0..15
    const int ch_row = tid >> 4;         // 0..19
    const int px0    = px_col * 8;       // 8 pixels per thread
    const int c0     = ch_row * 4;       // 4 channels per thread

    const int tile    = blockIdx.x;
    const int b       = (tile * PXT) >> 14;
    const int hw_base = (tile * PXT) & (HW - 1);

    const float* xp = x + ((size_t)b * D) * HW + hw_base + px0;
    const float2* wp = g_w2 + c0;        // +k*C per k row

    // acc[ch][px_pair], f32x2 packed over 2 adjacent pixels
    u64 acc[4][4];
    #pragma unroll
    for (int q = 0; q < 4; q++)
        #pragma unroll
        for (int p = 0; p < 4; p++) acc[q][p] = 0ULL;
    u64 n2[4] = {0ULL, 0ULL, 0ULL, 0ULL};   // ch_row 0 only

    #pragma unroll 1
    for (int kt = 0; kt < D; kt += 8) {
        #pragma unroll
        for (int kk = 0; kk < 8; kk++) {
            const int k = kt + kk;
            // 8 pixels = 2 x LDG.128 -> 4 packed pixel-pairs (register pairs)
            ulonglong2 xA = *reinterpret_cast<const ulonglong2*>(
                xp + (size_t)k * HW);
            ulonglong2 xB = *reinterpret_cast<const ulonglong2*>(
                xp + (size_t)k * HW + 4);
            // 4 duplicated channels = 2 x LDG.128 (warp-mostly-uniform, L1)
            ulonglong2 w01 = *reinterpret_cast<const ulonglong2*>(
                wp + (size_t)k * C);
            ulonglong2 w23 = *reinterpret_cast<const ulonglong2*>(
                wp + (size_t)k * C + 2);

            if (ch_row == 0) {
                n2[0] = fma2(xA.x, xA.x, n2[0]);
                n2[1] = fma2(xA.y, xA.y, n2[1]);
                n2[2] = fma2(xB.x, xB.x, n2[2]);
                n2[3] = fma2(xB.y, xB.y, n2[3]);
            }

            acc[0][0] = fma2(xA.x, w01.x, acc[0][0]);
            acc[0][1] = fma2(xA.y, w01.x, acc[0][1]);
            acc[0][2] = fma2(xB.x, w01.x, acc[0][2]);
            acc[0][3] = fma2(xB.y, w01.x, acc[0][3]);
            acc[1][0] = fma2(xA.x, w01.y, acc[1][0]);
            acc[1][1] = fma2(xA.y, w01.y, acc[1][1]);
            acc[1][2] = fma2(xB.x, w01.y, acc[1][2]);
            acc[1][3] = fma2(xB.y, w01.y, acc[1][3]);
            acc[2][0] = fma2(xA.x, w23.x, acc[2][0]);
            acc[2][1] = fma2(xA.y, w23.x, acc[2][1]);
            acc[2][2] = fma2(xB.x, w23.x, acc[2][2]);
            acc[2][3] = fma2(xB.y, w23.x, acc[2][3]);
            acc[3][0] = fma2(xA.x, w23.y, acc[3][0]);
            acc[3][1] = fma2(xA.y, w23.y, acc[3][1]);
            acc[3][2] = fma2(xB.x, w23.y, acc[3][2]);
            acc[3][3] = fma2(xB.y, w23.y, acc[3][3]);
        }
    }

    // ch_row 0 publishes inverse norms for its 8 pixels
    if (ch_row == 0) {
        #pragma unroll
        for (int p = 0; p < 4; p++) {
            float a, bb;
            unpack2(n2[p], a, bb);
            norms[px0 + 2 * p]     = 1.0f / fmaxf(sqrtf(a),  EPS);
            norms[px0 + 2 * p + 1] = 1.0f / fmaxf(sqrtf(bb), EPS);
        }
    }
    __syncthreads();

    float inv[8];
    #pragma unroll
    for (int i = 0; i < 8; i++) inv[i] = norms[px0 + i];

    // out[b][c][hw]: per channel, 8 contiguous pixels -> 2 x STG.128
    float* ob = out + ((size_t)b * C + c0) * HW + hw_base + px0;
    #pragma unroll
    for (int q = 0; q < 4; q++) {
        float v0, v1, v2, v3, v4, v5, v6, v7;
        unpack2(acc[q][0], v0, v1);
        unpack2(acc[q][1], v2, v3);
        unpack2(acc[q][2], v4, v5);
        unpack2(acc[q][3], v6, v7);
        float4 lo = make_float4(v0 * inv[0], v1 * inv[1], v2 * inv[2], v3 * inv[3]);
        float4 hi = make_float4(v4 * inv[4], v5 * inv[5], v6 * inv[6], v7 * inv[7]);
        float* oc = ob + (size_t)q * HW;
        *reinterpret_cast<float4*>(oc)     = lo;
        *reinterpret_cast<float4*>(oc + 4) = hi;
    }
}

// ---------------------------------------------------------------------------
// Launch
// ---------------------------------------------------------------------------
extern "C" void kernel_launch(void* const* d_in, const int* in_sizes, int n_in,
                              void* d_out, int out_size) {
    const float* x   = (const float*)d_in[0];  // [B, D, H, W]
    const float* w   = (const float*)d_in[1];  // [C, D]
    const float* asf = (const float*)d_in[2];  // [C]
    float* out = (float*)d_out;                // [B, C, H, W]

    prep_weights_kernel<<<C, D>>>(w, asf);
    coshead_main_kernel<<<NPIX / PXT, NTHREADS>>>(x, out);
}